// round 2
// baseline (speedup 1.0000x reference)
#include <cuda_runtime.h>
#include <cuda_bf16.h>

#define RESO   128
#define NRAYS  16384
#define NSAMP  192

// Warp-per-ray volume renderer, round 2.
// - Exact trip count precomputed (ray-box interval + exact fma-predicate adjust)
//   -> no per-sample bounds check.
// - lane c < 27 owns SH channel c ([x][y][z][27] layout -> coalesced corner loads).
// - Corner values cached in registers across samples sharing a cell (~50% hit).
// - Unconditional accumulate (lanes 0/9/18 read at the end) -> no predicates.
__global__ __launch_bounds__(128, 16) void render_kernel(
    const float* __restrict__ origins,
    const float* __restrict__ dirs,
    const float* __restrict__ density,
    const float* __restrict__ sh,
    float* __restrict__ out)
{
    const unsigned FULL = 0xffffffffu;
    int ray  = (blockIdx.x * blockDim.x + threadIdx.x) >> 5;
    int lane = threadIdx.x & 31;
    if (ray >= NRAYS) return;

    float ox = origins[3*ray+0], oy = origins[3*ray+1], oz = origins[3*ray+2];
    float dx = dirs[3*ray+0],    dy = dirs[3*ray+1],    dz = dirs[3*ray+2];

    // Per-lane SH basis coefficient, lane c -> basis[c % 9].
    float bl = 0.0f;
    {
        const float C0 = 0.28209479177387814f;
        const float C1 = 0.4886025119029199f;
        float b[9];
        b[0] = C0;
        b[1] = -C1 * dy;
        b[2] =  C1 * dz;
        b[3] = -C1 * dx;
        b[4] =  1.0925484305920792f * dx * dy;
        b[5] = -1.0925484305920792f * dy * dz;
        b[6] =  0.31539156525252005f * (2.0f*dz*dz - dx*dx - dy*dy);
        b[7] = -1.0925484305920792f * dx * dz;
        b[8] =  0.5462742152960396f * (dx*dx - dy*dy);
        if (lane < 27) bl = b[lane % 9];
    }

    // ---- Exact loop trip count ----------------------------------------------
    // The reference zeroes out-of-bounds contributions; with an interior origin
    // and a straight ray, in-bounds samples form a prefix. Estimate the exit t
    // analytically, then pin the boundary with the exact fma-based predicate so
    // the trip count matches the reference mask bit-for-bit.
    float tmax = 1e30f;
    {
        if (dx > 0.0f) tmax = fminf(tmax, (127.0f - ox) / dx);
        else if (dx < 0.0f) tmax = fminf(tmax, -ox / dx);
        if (dy > 0.0f) tmax = fminf(tmax, (127.0f - oy) / dy);
        else if (dy < 0.0f) tmax = fminf(tmax, -oy / dy);
        if (dz > 0.0f) tmax = fminf(tmax, (127.0f - oz) / dz);
        else if (dz < 0.0f) tmax = fminf(tmax, -oz / dz);
    }
    int n = (int)floorf(tmax * 2.0f + 0.5f);   // samples with t=(s+0.5)*0.5 <= tmax
    n = max(0, min(n, NSAMP));

    #define INB(s) ({                                                   \
        float _t  = ((float)(s) + 0.5f) * 0.5f;                         \
        float _px = fmaf(_t, dx, ox);                                   \
        float _py = fmaf(_t, dy, oy);                                   \
        float _pz = fmaf(_t, dz, oz);                                   \
        (_px >= 0.0f && _px <= 127.0f &&                                \
         _py >= 0.0f && _py <= 127.0f &&                                \
         _pz >= 0.0f && _pz <= 127.0f); })

    while (n > 0     && !INB(n - 1)) --n;   // shrink if estimate overshot
    while (n < NSAMP &&  INB(n))     ++n;   // grow if estimate undershot
    #undef INB

    // ---- March ---------------------------------------------------------------
    float accum = 0.0f;   // color partials read from lanes 0, 9, 18
    float T     = 1.0f;
    int   prev_cell = -1;
    float shc[8];
    float dn[8];
    const float* shl = sh + lane;           // lane-offset SH base

    #pragma unroll 1
    for (int s = 0; s < n; ++s) {
        float t  = ((float)s + 0.5f) * 0.5f;
        float px = fmaf(t, dx, ox);
        float py = fmaf(t, dy, oy);
        float pz = fmaf(t, dz, oz);

        float fx = floorf(px), fy = floorf(py), fz = floorf(pz);
        int ix = min((int)fx, RESO - 2);
        int iy = min((int)fy, RESO - 2);
        int iz = min((int)fz, RESO - 2);
        float ax = px - fx, ay = py - fy, az = pz - fz;

        int cell = (ix * RESO + iy) * RESO + iz;
        if (cell != prev_cell) {            // warp-uniform
            prev_cell = cell;
            const float* dp = density + cell;
            const float* sp = shl + cell * 27;
            // j bits: [2]=dx [1]=dy [0]=dz ; constant offsets -> immediate LDG
            dn[0] = __ldg(dp);           dn[1] = __ldg(dp + 1);
            dn[2] = __ldg(dp + 128);     dn[3] = __ldg(dp + 129);
            dn[4] = __ldg(dp + 16384);   dn[5] = __ldg(dp + 16385);
            dn[6] = __ldg(dp + 16512);   dn[7] = __ldg(dp + 16513);
            if (lane < 27) {
                shc[0] = __ldg(sp);              shc[1] = __ldg(sp + 27);
                shc[2] = __ldg(sp + 128*27);     shc[3] = __ldg(sp + 129*27);
                shc[4] = __ldg(sp + 16384*27);   shc[5] = __ldg(sp + 16385*27);
                shc[6] = __ldg(sp + 16512*27);   shc[7] = __ldg(sp + 16513*27);
            }
        }

        float wx0 = 1.0f - ax, wy0 = 1.0f - ay, wz0 = 1.0f - az;
        float w[8] = { wx0*wy0*wz0, wx0*wy0*az, wx0*ay*wz0, wx0*ay*az,
                       ax*wy0*wz0,  ax*wy0*az,  ax*ay*wz0,  ax*ay*az };

        float sigma = 0.0f, shv = 0.0f;
        #pragma unroll
        for (int j = 0; j < 8; ++j) {
            sigma = fmaf(w[j], dn[j],  sigma);
            shv   = fmaf(w[j], shc[j], shv);
        }

        if (sigma > 1e-10f) {               // warp-uniform (all lanes identical)
            float att = __expf(-0.5f * sigma);
            float wgt = T * (1.0f - att);
            T *= att;

            // Sum shv*bl over lane groups {0..8},{9..17},{18..26}.
            float p = (lane < 27) ? shv * bl : 0.0f;
            float v = p;
            v += __shfl_down_sync(FULL, v, 1);
            v += __shfl_down_sync(FULL, v, 2);
            v += __shfl_down_sync(FULL, v, 4);          // lane b: sum p[b..b+7]
            v += __shfl_sync(FULL, p, (lane + 8) & 31); // + p[b+8]
            float rgb = fmaxf(v + 0.5f, 0.0f);
            accum = fmaf(wgt, rgb, accum);              // only lanes 0/9/18 read
        }
    }

    float r1 = __shfl_sync(FULL, accum, 9);
    float r2 = __shfl_sync(FULL, accum, 18);
    if (lane == 0) {
        out[3*ray+0] = accum + T;
        out[3*ray+1] = r1    + T;
        out[3*ray+2] = r2    + T;
    }
}

extern "C" void kernel_launch(void* const* d_in, const int* in_sizes, int n_in,
                              void* d_out, int out_size)
{
    const float* origins = (const float*)d_in[0];
    const float* dirs    = (const float*)d_in[1];
    const float* density = (const float*)d_in[2];
    const float* sh      = (const float*)d_in[3];
    float* out = (float*)d_out;

    // 4 warps (4 rays) per block -> finer retirement granularity for the tail
    render_kernel<<<NRAYS / 4, 128>>>(origins, dirs, density, sh, out);
}

// round 3
// speedup vs baseline: 1.4187x; 1.4187x over previous
#include <cuda_runtime.h>
#include <cuda_bf16.h>

#define RESO   128
#define NRAYS  16384
#define NSAMP  192

// Warp-per-ray volume renderer, round 3.
// Key change vs round 2: NO occupancy-forcing launch bounds -> ptxas may hold
// all corner values in registers (rounds 1-2 were capped at 32 regs and spilled
// the corner arrays to local memory, which is what the 69% L1 throughput was).
__global__ __launch_bounds__(256) void render_kernel(
    const float* __restrict__ origins,
    const float* __restrict__ dirs,
    const float* __restrict__ density,
    const float* __restrict__ sh,
    float* __restrict__ out)
{
    const unsigned FULL = 0xffffffffu;
    int ray  = (blockIdx.x * blockDim.x + threadIdx.x) >> 5;
    int lane = threadIdx.x & 31;
    if (ray >= NRAYS) return;

    float ox = origins[3*ray+0], oy = origins[3*ray+1], oz = origins[3*ray+2];
    float dx = dirs[3*ray+0],    dy = dirs[3*ray+1],    dz = dirs[3*ray+2];

    // Per-lane SH basis coefficient, lane c -> basis[c % 9].
    float bl = 0.0f;
    {
        const float C0 = 0.28209479177387814f;
        const float C1 = 0.4886025119029199f;
        float b[9];
        b[0] = C0;
        b[1] = -C1 * dy;
        b[2] =  C1 * dz;
        b[3] = -C1 * dx;
        b[4] =  1.0925484305920792f * dx * dy;
        b[5] = -1.0925484305920792f * dy * dz;
        b[6] =  0.31539156525252005f * (2.0f*dz*dz - dx*dx - dy*dy);
        b[7] = -1.0925484305920792f * dx * dz;
        b[8] =  0.5462742152960396f * (dx*dx - dy*dy);
        if (lane < 27) bl = b[lane % 9];
    }

    // ---- Exact loop trip count (in-bounds samples form a prefix) ------------
    float tmax = 1e30f;
    {
        if (dx > 0.0f) tmax = fminf(tmax, (127.0f - ox) / dx);
        else if (dx < 0.0f) tmax = fminf(tmax, -ox / dx);
        if (dy > 0.0f) tmax = fminf(tmax, (127.0f - oy) / dy);
        else if (dy < 0.0f) tmax = fminf(tmax, -oy / dy);
        if (dz > 0.0f) tmax = fminf(tmax, (127.0f - oz) / dz);
        else if (dz < 0.0f) tmax = fminf(tmax, -oz / dz);
    }
    int n = (int)floorf(tmax * 2.0f + 0.5f);
    n = max(0, min(n, NSAMP));

    #define INB(s) ({                                                   \
        float _t  = ((float)(s) + 0.5f) * 0.5f;                         \
        float _px = fmaf(_t, dx, ox);                                   \
        float _py = fmaf(_t, dy, oy);                                   \
        float _pz = fmaf(_t, dz, oz);                                   \
        (_px >= 0.0f && _px <= 127.0f &&                                \
         _py >= 0.0f && _py <= 127.0f &&                                \
         _pz >= 0.0f && _pz <= 127.0f); })

    while (n > 0     && !INB(n - 1)) --n;   // pin boundary with exact predicate
    while (n < NSAMP &&  INB(n))     ++n;
    #undef INB

    // ---- March ---------------------------------------------------------------
    float accum = 0.0f;   // color partials read from lanes 0, 9, 18
    float T     = 1.0f;
    int   prev_cell = -1;
    // Corner values as named scalars -> guaranteed register-resident.
    float d0=0,d1=0,d2=0,d3=0,d4=0,d5=0,d6=0,d7=0;
    float s0=0,s1=0,s2=0,s3=0,s4=0,s5=0,s6=0,s7=0;
    const float* shl = sh + lane;

    #pragma unroll 1
    for (int s = 0; s < n; ++s) {
        float t  = ((float)s + 0.5f) * 0.5f;
        float px = fmaf(t, dx, ox);
        float py = fmaf(t, dy, oy);
        float pz = fmaf(t, dz, oz);

        float fx = floorf(px), fy = floorf(py), fz = floorf(pz);
        int ix = min((int)fx, RESO - 2);
        int iy = min((int)fy, RESO - 2);
        int iz = min((int)fz, RESO - 2);
        float ax = px - fx, ay = py - fy, az = pz - fz;

        int cell = (ix * RESO + iy) * RESO + iz;
        if (cell != prev_cell) {            // warp-uniform
            prev_cell = cell;
            const float* dp = density + cell;
            const float* sp = shl + cell * 27;
            // corner bit order: [2]=dx [1]=dy [0]=dz (matches reference)
            d0 = __ldg(dp);           d1 = __ldg(dp + 1);
            d2 = __ldg(dp + 128);     d3 = __ldg(dp + 129);
            d4 = __ldg(dp + 16384);   d5 = __ldg(dp + 16385);
            d6 = __ldg(dp + 16512);   d7 = __ldg(dp + 16513);
            if (lane < 27) {
                s0 = __ldg(sp);              s1 = __ldg(sp + 27);
                s2 = __ldg(sp + 128*27);     s3 = __ldg(sp + 129*27);
                s4 = __ldg(sp + 16384*27);   s5 = __ldg(sp + 16385*27);
                s6 = __ldg(sp + 16512*27);   s7 = __ldg(sp + 16513*27);
            }
        }

        float bx = 1.0f - ax, by = 1.0f - ay, bz = 1.0f - az;
        float w0 = bx*by*bz, w1 = bx*by*az, w2 = bx*ay*bz, w3 = bx*ay*az;
        float w4 = ax*by*bz, w5 = ax*by*az, w6 = ax*ay*bz, w7 = ax*ay*az;

        float sigma = w0*d0; float shv = w0*s0;
        sigma = fmaf(w1,d1,sigma); shv = fmaf(w1,s1,shv);
        sigma = fmaf(w2,d2,sigma); shv = fmaf(w2,s2,shv);
        sigma = fmaf(w3,d3,sigma); shv = fmaf(w3,s3,shv);
        sigma = fmaf(w4,d4,sigma); shv = fmaf(w4,s4,shv);
        sigma = fmaf(w5,d5,sigma); shv = fmaf(w5,s5,shv);
        sigma = fmaf(w6,d6,sigma); shv = fmaf(w6,s6,shv);
        sigma = fmaf(w7,d7,sigma); shv = fmaf(w7,s7,shv);

        if (sigma > 1e-10f) {               // warp-uniform
            float att = __expf(-0.5f * sigma);
            float wgt = T * (1.0f - att);
            T *= att;

            // Sum shv*bl over lane groups {0..8},{9..17},{18..26}.
            float p = (lane < 27) ? shv * bl : 0.0f;
            float v = p;
            v += __shfl_down_sync(FULL, v, 1);
            v += __shfl_down_sync(FULL, v, 2);
            v += __shfl_down_sync(FULL, v, 4);          // lane b: sum p[b..b+7]
            v += __shfl_sync(FULL, p, (lane + 8) & 31); // + p[b+8]
            float rgb = fmaxf(v + 0.5f, 0.0f);
            accum = fmaf(wgt, rgb, accum);              // lanes 0/9/18 read later
        }
    }

    float r1 = __shfl_sync(FULL, accum, 9);
    float r2 = __shfl_sync(FULL, accum, 18);
    if (lane == 0) {
        out[3*ray+0] = accum + T;
        out[3*ray+1] = r1    + T;
        out[3*ray+2] = r2    + T;
    }
}

extern "C" void kernel_launch(void* const* d_in, const int* in_sizes, int n_in,
                              void* d_out, int out_size)
{
    const float* origins = (const float*)d_in[0];
    const float* dirs    = (const float*)d_in[1];
    const float* density = (const float*)d_in[2];
    const float* sh      = (const float*)d_in[3];
    float* out = (float*)d_out;

    render_kernel<<<NRAYS / 8, 256>>>(origins, dirs, density, sh, out);
}

// round 4
// speedup vs baseline: 1.5383x; 1.0843x over previous
#include <cuda_runtime.h>
#include <cuda_bf16.h>

#define RESO   128
#define NRAYS  16384
#define NSAMP  192

// Warp-per-ray volume renderer, round 4.
// Change vs round 3: 64-thread blocks (2 rays/block). A block retires when its
// longest ray ends; with 8 rays/block the spread in ray lengths parked most
// warp slots (achieved occ 38% vs 62.5% theoretical). 2 rays/block cuts the
// retirement quantum 4x.
__global__ __launch_bounds__(64) void render_kernel(
    const float* __restrict__ origins,
    const float* __restrict__ dirs,
    const float* __restrict__ density,
    const float* __restrict__ sh,
    float* __restrict__ out)
{
    const unsigned FULL = 0xffffffffu;
    int ray  = (blockIdx.x * blockDim.x + threadIdx.x) >> 5;
    int lane = threadIdx.x & 31;
    if (ray >= NRAYS) return;

    float ox = origins[3*ray+0], oy = origins[3*ray+1], oz = origins[3*ray+2];
    float dx = dirs[3*ray+0],    dy = dirs[3*ray+1],    dz = dirs[3*ray+2];

    // Per-lane SH basis coefficient, lane c -> basis[c % 9].
    float bl = 0.0f;
    {
        const float C0 = 0.28209479177387814f;
        const float C1 = 0.4886025119029199f;
        float b[9];
        b[0] = C0;
        b[1] = -C1 * dy;
        b[2] =  C1 * dz;
        b[3] = -C1 * dx;
        b[4] =  1.0925484305920792f * dx * dy;
        b[5] = -1.0925484305920792f * dy * dz;
        b[6] =  0.31539156525252005f * (2.0f*dz*dz - dx*dx - dy*dy);
        b[7] = -1.0925484305920792f * dx * dz;
        b[8] =  0.5462742152960396f * (dx*dx - dy*dy);
        if (lane < 27) bl = b[lane % 9];
    }

    // ---- Exact loop trip count (in-bounds samples form a prefix) ------------
    float tmax = 1e30f;
    {
        if (dx > 0.0f) tmax = fminf(tmax, (127.0f - ox) / dx);
        else if (dx < 0.0f) tmax = fminf(tmax, -ox / dx);
        if (dy > 0.0f) tmax = fminf(tmax, (127.0f - oy) / dy);
        else if (dy < 0.0f) tmax = fminf(tmax, -oy / dy);
        if (dz > 0.0f) tmax = fminf(tmax, (127.0f - oz) / dz);
        else if (dz < 0.0f) tmax = fminf(tmax, -oz / dz);
    }
    int n = (int)floorf(tmax * 2.0f + 0.5f);
    n = max(0, min(n, NSAMP));

    #define INB(s) ({                                                   \
        float _t  = ((float)(s) + 0.5f) * 0.5f;                         \
        float _px = fmaf(_t, dx, ox);                                   \
        float _py = fmaf(_t, dy, oy);                                   \
        float _pz = fmaf(_t, dz, oz);                                   \
        (_px >= 0.0f && _px <= 127.0f &&                                \
         _py >= 0.0f && _py <= 127.0f &&                                \
         _pz >= 0.0f && _pz <= 127.0f); })

    while (n > 0     && !INB(n - 1)) --n;   // pin boundary with exact predicate
    while (n < NSAMP &&  INB(n))     ++n;
    #undef INB

    // ---- March ---------------------------------------------------------------
    float accum = 0.0f;   // color partials read from lanes 0, 9, 18
    float T     = 1.0f;
    int   prev_cell = -1;
    float d0=0,d1=0,d2=0,d3=0,d4=0,d5=0,d6=0,d7=0;   // density corners (regs)
    float s0=0,s1=0,s2=0,s3=0,s4=0,s5=0,s6=0,s7=0;   // SH corners, this lane's ch
    const float* shl = sh + lane;

    #pragma unroll 1
    for (int s = 0; s < n; ++s) {
        float t  = ((float)s + 0.5f) * 0.5f;
        float px = fmaf(t, dx, ox);
        float py = fmaf(t, dy, oy);
        float pz = fmaf(t, dz, oz);

        float fx = floorf(px), fy = floorf(py), fz = floorf(pz);
        int ix = min((int)fx, RESO - 2);
        int iy = min((int)fy, RESO - 2);
        int iz = min((int)fz, RESO - 2);
        float ax = px - fx, ay = py - fy, az = pz - fz;

        int cell = (ix * RESO + iy) * RESO + iz;
        if (cell != prev_cell) {            // warp-uniform
            prev_cell = cell;
            const float* dp = density + cell;
            const float* sp = shl + cell * 27;
            // corner bit order: [2]=dx [1]=dy [0]=dz (matches reference)
            d0 = __ldg(dp);           d1 = __ldg(dp + 1);
            d2 = __ldg(dp + 128);     d3 = __ldg(dp + 129);
            d4 = __ldg(dp + 16384);   d5 = __ldg(dp + 16385);
            d6 = __ldg(dp + 16512);   d7 = __ldg(dp + 16513);
            if (lane < 27) {
                s0 = __ldg(sp);              s1 = __ldg(sp + 27);
                s2 = __ldg(sp + 128*27);     s3 = __ldg(sp + 129*27);
                s4 = __ldg(sp + 16384*27);   s5 = __ldg(sp + 16385*27);
                s6 = __ldg(sp + 16512*27);   s7 = __ldg(sp + 16513*27);
            }
        }

        float bx = 1.0f - ax, by = 1.0f - ay, bz = 1.0f - az;
        float w0 = bx*by*bz, w1 = bx*by*az, w2 = bx*ay*bz, w3 = bx*ay*az;
        float w4 = ax*by*bz, w5 = ax*by*az, w6 = ax*ay*bz, w7 = ax*ay*az;

        float sigma = w0*d0; float shv = w0*s0;
        sigma = fmaf(w1,d1,sigma); shv = fmaf(w1,s1,shv);
        sigma = fmaf(w2,d2,sigma); shv = fmaf(w2,s2,shv);
        sigma = fmaf(w3,d3,sigma); shv = fmaf(w3,s3,shv);
        sigma = fmaf(w4,d4,sigma); shv = fmaf(w4,s4,shv);
        sigma = fmaf(w5,d5,sigma); shv = fmaf(w5,s5,shv);
        sigma = fmaf(w6,d6,sigma); shv = fmaf(w6,s6,shv);
        sigma = fmaf(w7,d7,sigma); shv = fmaf(w7,s7,shv);

        if (sigma > 1e-10f) {               // warp-uniform
            float att = __expf(-0.5f * sigma);
            float wgt = T * (1.0f - att);
            T *= att;

            // Sum shv*bl over lane groups {0..8},{9..17},{18..26}.
            float p = (lane < 27) ? shv * bl : 0.0f;
            float v = p;
            v += __shfl_down_sync(FULL, v, 1);
            v += __shfl_down_sync(FULL, v, 2);
            v += __shfl_down_sync(FULL, v, 4);          // lane b: sum p[b..b+7]
            v += __shfl_sync(FULL, p, (lane + 8) & 31); // + p[b+8]
            float rgb = fmaxf(v + 0.5f, 0.0f);
            accum = fmaf(wgt, rgb, accum);              // lanes 0/9/18 read later
        }
    }

    float r1 = __shfl_sync(FULL, accum, 9);
    float r2 = __shfl_sync(FULL, accum, 18);
    if (lane == 0) {
        out[3*ray+0] = accum + T;
        out[3*ray+1] = r1    + T;
        out[3*ray+2] = r2    + T;
    }
}

extern "C" void kernel_launch(void* const* d_in, const int* in_sizes, int n_in,
                              void* d_out, int out_size)
{
    const float* origins = (const float*)d_in[0];
    const float* dirs    = (const float*)d_in[1];
    const float* density = (const float*)d_in[2];
    const float* sh      = (const float*)d_in[3];
    float* out = (float*)d_out;

    // 2 rays per 64-thread block -> fine-grained block retirement
    render_kernel<<<NRAYS / 2, 64>>>(origins, dirs, density, sh, out);
}

// round 5
// speedup vs baseline: 1.6584x; 1.0781x over previous
#include <cuda_runtime.h>
#include <cuda_bf16.h>

#define RESO   128
#define NRAYS  16384
#define NSAMP  192

// Round 5: persistent kernel + warp-granular dynamic work stealing.
// Rounds 3-4 showed occupancy (38-43%) as the limiter: static ray->block
// assignment parks finished warps behind long-ray siblings and quantizes the
// grid into 2.6 waves. Here every warp pulls rays from a global counter until
// the pool drains; the tail shrinks to ~one ray's march.

__device__ unsigned g_ray_counter;

__global__ void reset_counter_kernel() { g_ray_counter = 0u; }

__global__ __launch_bounds__(128) void render_kernel(
    const float* __restrict__ origins,
    const float* __restrict__ dirs,
    const float* __restrict__ density,
    const float* __restrict__ sh,
    float* __restrict__ out)
{
    const unsigned FULL = 0xffffffffu;
    int lane = threadIdx.x & 31;
    const float* shl = sh + lane;

    for (;;) {
        // ---- steal a ray -----------------------------------------------------
        unsigned ray;
        if (lane == 0) ray = atomicAdd(&g_ray_counter, 1u);
        ray = __shfl_sync(FULL, ray, 0);
        if (ray >= NRAYS) break;

        float ox = origins[3*ray+0], oy = origins[3*ray+1], oz = origins[3*ray+2];
        float dx = dirs[3*ray+0],    dy = dirs[3*ray+1],    dz = dirs[3*ray+2];

        // Per-lane SH basis coefficient, lane c -> basis[c % 9].
        float bl = 0.0f;
        {
            const float C0 = 0.28209479177387814f;
            const float C1 = 0.4886025119029199f;
            float b[9];
            b[0] = C0;
            b[1] = -C1 * dy;
            b[2] =  C1 * dz;
            b[3] = -C1 * dx;
            b[4] =  1.0925484305920792f * dx * dy;
            b[5] = -1.0925484305920792f * dy * dz;
            b[6] =  0.31539156525252005f * (2.0f*dz*dz - dx*dx - dy*dy);
            b[7] = -1.0925484305920792f * dx * dz;
            b[8] =  0.5462742152960396f * (dx*dx - dy*dy);
            if (lane < 27) bl = b[lane % 9];
        }

        // ---- exact trip count (in-bounds samples form a prefix) -------------
        float tmax = 1e30f;
        if (dx > 0.0f) tmax = fminf(tmax, (127.0f - ox) / dx);
        else if (dx < 0.0f) tmax = fminf(tmax, -ox / dx);
        if (dy > 0.0f) tmax = fminf(tmax, (127.0f - oy) / dy);
        else if (dy < 0.0f) tmax = fminf(tmax, -oy / dy);
        if (dz > 0.0f) tmax = fminf(tmax, (127.0f - oz) / dz);
        else if (dz < 0.0f) tmax = fminf(tmax, -oz / dz);

        int n = (int)floorf(tmax * 2.0f + 0.5f);
        n = max(0, min(n, NSAMP));

        #define INB(s) ({                                                   \
            float _t  = ((float)(s) + 0.5f) * 0.5f;                         \
            float _px = fmaf(_t, dx, ox);                                   \
            float _py = fmaf(_t, dy, oy);                                   \
            float _pz = fmaf(_t, dz, oz);                                   \
            (_px >= 0.0f && _px <= 127.0f &&                                \
             _py >= 0.0f && _py <= 127.0f &&                                \
             _pz >= 0.0f && _pz <= 127.0f); })

        while (n > 0     && !INB(n - 1)) --n;  // pin boundary w/ exact predicate
        while (n < NSAMP &&  INB(n))     ++n;
        #undef INB

        // ---- march ----------------------------------------------------------
        float accum = 0.0f;   // color partials read from lanes 0, 9, 18
        float T     = 1.0f;
        int   prev_cell = -1;
        float d0=0,d1=0,d2=0,d3=0,d4=0,d5=0,d6=0,d7=0;
        float s0=0,s1=0,s2=0,s3=0,s4=0,s5=0,s6=0,s7=0;

        #pragma unroll 1
        for (int s = 0; s < n; ++s) {
            float t  = ((float)s + 0.5f) * 0.5f;
            float px = fmaf(t, dx, ox);
            float py = fmaf(t, dy, oy);
            float pz = fmaf(t, dz, oz);

            float fx = floorf(px), fy = floorf(py), fz = floorf(pz);
            int ix = min((int)fx, RESO - 2);
            int iy = min((int)fy, RESO - 2);
            int iz = min((int)fz, RESO - 2);
            float ax = px - fx, ay = py - fy, az = pz - fz;

            int cell = (ix * RESO + iy) * RESO + iz;
            if (cell != prev_cell) {            // warp-uniform
                prev_cell = cell;
                const float* dp = density + cell;
                const float* sp = shl + cell * 27;
                // corner bit order: [2]=dx [1]=dy [0]=dz (matches reference)
                d0 = __ldg(dp);           d1 = __ldg(dp + 1);
                d2 = __ldg(dp + 128);     d3 = __ldg(dp + 129);
                d4 = __ldg(dp + 16384);   d5 = __ldg(dp + 16385);
                d6 = __ldg(dp + 16512);   d7 = __ldg(dp + 16513);
                if (lane < 27) {
                    s0 = __ldg(sp);              s1 = __ldg(sp + 27);
                    s2 = __ldg(sp + 128*27);     s3 = __ldg(sp + 129*27);
                    s4 = __ldg(sp + 16384*27);   s5 = __ldg(sp + 16385*27);
                    s6 = __ldg(sp + 16512*27);   s7 = __ldg(sp + 16513*27);
                }
            }

            float bx = 1.0f - ax, by = 1.0f - ay, bz = 1.0f - az;
            float w0 = bx*by*bz, w1 = bx*by*az, w2 = bx*ay*bz, w3 = bx*ay*az;
            float w4 = ax*by*bz, w5 = ax*by*az, w6 = ax*ay*bz, w7 = ax*ay*az;

            float sigma = w0*d0; float shv = w0*s0;
            sigma = fmaf(w1,d1,sigma); shv = fmaf(w1,s1,shv);
            sigma = fmaf(w2,d2,sigma); shv = fmaf(w2,s2,shv);
            sigma = fmaf(w3,d3,sigma); shv = fmaf(w3,s3,shv);
            sigma = fmaf(w4,d4,sigma); shv = fmaf(w4,s4,shv);
            sigma = fmaf(w5,d5,sigma); shv = fmaf(w5,s5,shv);
            sigma = fmaf(w6,d6,sigma); shv = fmaf(w6,s6,shv);
            sigma = fmaf(w7,d7,sigma); shv = fmaf(w7,s7,shv);

            if (sigma > 1e-10f) {               // warp-uniform
                float att = __expf(-0.5f * sigma);
                float wgt = T * (1.0f - att);
                T *= att;

                // Sum shv*bl over lane groups {0..8},{9..17},{18..26}.
                float p = (lane < 27) ? shv * bl : 0.0f;
                float v = p;
                v += __shfl_down_sync(FULL, v, 1);
                v += __shfl_down_sync(FULL, v, 2);
                v += __shfl_down_sync(FULL, v, 4);          // lane b: p[b..b+7]
                v += __shfl_sync(FULL, p, (lane + 8) & 31); // + p[b+8]
                float rgb = fmaxf(v + 0.5f, 0.0f);
                accum = fmaf(wgt, rgb, accum);              // lanes 0/9/18 read
            }
        }

        float r1 = __shfl_sync(FULL, accum, 9);
        float r2 = __shfl_sync(FULL, accum, 18);
        if (lane == 0) {
            out[3*ray+0] = accum + T;
            out[3*ray+1] = r1    + T;
            out[3*ray+2] = r2    + T;
        }
    }
}

extern "C" void kernel_launch(void* const* d_in, const int* in_sizes, int n_in,
                              void* d_out, int out_size)
{
    const float* origins = (const float*)d_in[0];
    const float* dirs    = (const float*)d_in[1];
    const float* density = (const float*)d_in[2];
    const float* sh      = (const float*)d_in[3];
    float* out = (float*)d_out;

    reset_counter_kernel<<<1, 1>>>();
    // Persistent-ish: ~10 blocks/SM resident at ~48 regs; 1480 blocks on 148
    // SMs -> single wave, warps steal rays until the pool drains.
    render_kernel<<<1480, 128>>>(origins, dirs, density, sh, out);
}